// round 17
// baseline (speedup 1.0000x reference)
#include <cuda_runtime.h>
#include <cuda_fp16.h>
#include <cstdint>

// ---------------------------------------------------------------------------
// Problem constants
// ---------------------------------------------------------------------------
#define B_ROWS 4096
#define D_DIM  512
#define C_DIM  20000

#define BM 128
#define BN 128
#define BK 64                   // 64 fp16 = 128B rows (SW128 atom)
#define NK (D_DIM / BK)         // 8 k-iterations
#define STAGES 3
#define THREADS 256

#define STAGE_BYTES ((BM + BN) * BK * 2)   // 32768
#define SMEM_BYTES  (STAGES * STAGE_BYTES + 1024)

static __device__ __half g_f16[(size_t)B_ROWS * D_DIM];   // normalized feat, fp16
static __device__ __half g_w16[(size_t)C_DIM * D_DIM];    // normalized weights, fp16

// ArcFace constants
#define AF_SCALE  30.0f
#define AF_COSM   0.87758256189037271612f   // cos(0.5)
#define AF_SINM   0.47942553860420300027f   // sin(0.5)
#define AF_THRESH (-0.87758256189037271612f)
#define AF_EXTV   (-0.23971276930210150013f) // -0.5*sin(0.5)

// ---------------------------------------------------------------------------
// PTX helpers
// ---------------------------------------------------------------------------
__device__ __forceinline__ uint32_t smem_u32(const void* p) {
    uint32_t a;
    asm("{ .reg .u64 t; cvta.to.shared.u64 t, %1; cvt.u32.u64 %0, t; }"
        : "=r"(a) : "l"(p));
    return a;
}

__device__ __forceinline__ void cp16(uint32_t dst, const void* src) {
    asm volatile("cp.async.cg.shared.global [%0], [%1], 16;"
                 :: "r"(dst), "l"(src));
}
__device__ __forceinline__ void cp16z(uint32_t dst, const void* src,
                                      uint32_t ssize) {
    asm volatile("cp.async.cg.shared.global [%0], [%1], 16, %2;"
                 :: "r"(dst), "l"(src), "r"(ssize));
}
#define CP_COMMIT() asm volatile("cp.async.commit_group;" ::: "memory")
#define CP_WAIT(n)  asm volatile("cp.async.wait_group %0;" :: "n"(n) : "memory")

#define LDSM_X4(r, addr) \
    asm volatile("ldmatrix.sync.aligned.m8n8.x4.shared.b16 {%0,%1,%2,%3}, [%4];" \
        : "=r"((r)[0]), "=r"((r)[1]), "=r"((r)[2]), "=r"((r)[3]) : "r"(addr))

__device__ __forceinline__ void mma_16816(float* d, const uint32_t* a,
                                          uint32_t b0, uint32_t b1) {
    asm volatile(
        "mma.sync.aligned.m16n8k16.row.col.f32.f16.f16.f32 "
        "{%0,%1,%2,%3}, {%4,%5,%6,%7}, {%8,%9}, {%0,%1,%2,%3};"
        : "+f"(d[0]), "+f"(d[1]), "+f"(d[2]), "+f"(d[3])
        : "r"(a[0]), "r"(a[1]), "r"(a[2]), "r"(a[3]), "r"(b0), "r"(b1));
}

__device__ __forceinline__ void st_cs_f2(float* p, float x, float y) {
    asm volatile("st.global.cs.v2.f32 [%0], {%1, %2};"
                 :: "l"(p), "f"(x), "f"(y) : "memory");
}

// PDL: no-ops when the kernel is not launched with programmatic dependency.
#define GRIDDEP_WAIT() \
    asm volatile("griddepcontrol.wait;" ::: "memory")
#define GRIDDEP_LAUNCH_DEPENDENTS() \
    asm volatile("griddepcontrol.launch_dependents;" ::: "memory")

// ---------------------------------------------------------------------------
// Kernel 1: row L2-normalize fp32 -> fp16, warp-per-row (no smem, no barrier).
// Each lane: 4 float4 loads (MLP=4), shfl-xor reduce, 4 uint2 stores.
// ---------------------------------------------------------------------------
__global__ void __launch_bounds__(512)
norm_rows_kernel(const float* __restrict__ feat,
                 const float* __restrict__ wts) {
    const int lane = threadIdx.x & 31;
    int row = blockIdx.x * 16 + (threadIdx.x >> 5);
    const float* src;
    __half* dst;
    bool active = true;
    if (row < B_ROWS) {
        src = feat + (size_t)row * D_DIM;
        dst = g_f16 + (size_t)row * D_DIM;
    } else {
        row -= B_ROWS;
        if (row >= C_DIM) active = false;
        src = wts + (size_t)(active ? row : 0) * D_DIM;
        dst = g_w16 + (size_t)(active ? row : 0) * D_DIM;
    }

    if (active) {
        float4 v[4];
        const float4* p = reinterpret_cast<const float4*>(src);
        #pragma unroll
        for (int i = 0; i < 4; i++) v[i] = p[lane + i * 32];

        float ss = 0.0f;
        #pragma unroll
        for (int i = 0; i < 4; i++)
            ss += v[i].x * v[i].x + v[i].y * v[i].y +
                  v[i].z * v[i].z + v[i].w * v[i].w;
        #pragma unroll
        for (int o = 16; o; o >>= 1) ss += __shfl_xor_sync(0xFFFFFFFFu, ss, o);

        const float inv = rsqrtf(ss);
        uint2* q = reinterpret_cast<uint2*>(dst);
        #pragma unroll
        for (int i = 0; i < 4; i++) {
            __half2 h0 = __floats2half2_rn(v[i].x * inv, v[i].y * inv);
            __half2 h1 = __floats2half2_rn(v[i].z * inv, v[i].w * inv);
            uint2 pk;
            pk.x = *reinterpret_cast<uint32_t*>(&h0);
            pk.y = *reinterpret_cast<uint32_t*>(&h1);
            q[lane + i * 32] = pk;
        }
    }
    // signal PDL dependents (GEMM) — data stores above are complete per-thread
    GRIDDEP_LAUNCH_DEPENDENTS();
}

// ---------------------------------------------------------------------------
// ArcFace margin for the label column
// ---------------------------------------------------------------------------
__device__ __forceinline__ float af_margin(float c) {
    if (c > AF_THRESH) {
        float s = sqrtf(fmaxf(0.0f, 1.0f - c * c));
        return AF_SCALE * (c * AF_COSM - s * AF_SINM);
    }
    return AF_SCALE * (c + AF_EXTV);
}

// ---------------------------------------------------------------------------
// GEMM tile body (R15/R16 mainloop, UNCHANGED — 285us, ~98% of the HMMA wall):
// 128x128 CTA tile, 8 warps as 2m x 4n, 3-stage cp.async, 2 CTAs/SM,
// fp32 accumulators, fragment double-buffering across ks.
// ---------------------------------------------------------------------------
template <bool FULL>
__device__ __forceinline__ void gemm_tile(const int* __restrict__ label,
                                          float* __restrict__ cos_out,
                                          float* __restrict__ marg_out,
                                          uint32_t sbase, int m0, int n0) {
    const int tid  = threadIdx.x;
    const int lane = tid & 31;
    const int wid  = tid >> 5;
    const int warp_m = wid & 1;     // 0..1  (64-row slab)
    const int warp_n = wid >> 1;    // 0..3  (32-col slab)

    // ---- loader bases (per thread) ----
    const int c16 = tid & 7;
    const int rq  = tid >> 3;
    const uint32_t dA = sbase + (uint32_t)(rq * 128 + ((c16 * 16) ^ ((rq & 7) << 4)));
    const uint32_t dB = dA + 16384;

    const __half* aSrc = g_f16 + (size_t)(m0 + rq) * D_DIM + c16 * 8;
    const __half* bSrc = nullptr;
    const __half* bSrcT[4];
    uint32_t bSz[4];
    if constexpr (FULL) {
        bSrc = g_w16 + (size_t)(n0 + rq) * D_DIM + c16 * 8;
    } else {
        #pragma unroll
        for (int i = 0; i < 4; i++) {
            int n = n0 + rq + i * 32;
            bSrcT[i] = g_w16 + (size_t)((n < C_DIM) ? n : 0) * D_DIM + c16 * 8;
            bSz[i]   = (n < C_DIM) ? 16u : 0u;
        }
    }

    // ---- ldmatrix bases (XOR-derived per-ks column) ----
    const uint32_t col0 =
        ((uint32_t)((lane >> 4) * 16)) ^ ((uint32_t)((lane & 7) << 4));
    const uint32_t a_row = sbase + (uint32_t)((warp_m * 64 + (lane & 15)) * 128);
    const uint32_t b_row = sbase + 16384u + (uint32_t)((warp_n * 32 + (lane & 15)) * 128);

    float acc[4][4][4];
    #pragma unroll
    for (int mt = 0; mt < 4; mt++)
        #pragma unroll
        for (int nt = 0; nt < 4; nt++)
            #pragma unroll
            for (int e = 0; e < 4; e++) acc[mt][nt][e] = 0.0f;

    auto load_stage = [&](int st, int kk) {
        #pragma unroll
        for (int i = 0; i < 4; i++)
            cp16(dA + st * STAGE_BYTES + i * 4096, aSrc + kk + i * 16384);
        #pragma unroll
        for (int i = 0; i < 4; i++) {
            if constexpr (FULL)
                cp16(dB + st * STAGE_BYTES + i * 4096, bSrc + kk + i * 16384);
            else
                cp16z(dB + st * STAGE_BYTES + i * 4096, bSrcT[i] + kk, bSz[i]);
        }
    };

    // PDL: block here (not at launch) until norm kernel's data is ready.
    // All code above is address math with no dependence on g_f16/g_w16 data.
    GRIDDEP_WAIT();

    // prologue: stages 0,1
    load_stage(0, 0);  CP_COMMIT();
    load_stage(1, BK); CP_COMMIT();

    // double-buffered fragment sets
    uint32_t afr[2][4][4];
    uint32_t bfr[2][2][4];

    #pragma unroll
    for (int k = 0; k < NK; k++) {
        CP_WAIT(1);
        __syncthreads();

        const int st = (k % STAGES) * STAGE_BYTES;   // immediate under unroll
        const uint32_t aB = a_row + st;
        const uint32_t bB = b_row + st;

        // preload ks=0 fragments
        {
            const uint32_t c = col0;
            #pragma unroll
            for (int mt = 0; mt < 4; mt++)
                LDSM_X4(afr[0][mt], aB + c + mt * 2048);
            #pragma unroll
            for (int g = 0; g < 2; g++)
                LDSM_X4(bfr[0][g], bB + c + g * 2048);
        }

        // issue next-stage global prefetch while frags are in flight
        if (k + 2 < NK) load_stage((k + 2) % STAGES, (k + 2) * BK);
        CP_COMMIT();   // empty group in drain iters keeps wait count uniform

        #pragma unroll
        for (int ks = 0; ks < 4; ks++) {
            const int cur = ks & 1;
            if (ks < 3) {
                const int nxt = cur ^ 1;
                const uint32_t c = col0 ^ (uint32_t)((ks + 1) << 5);
                #pragma unroll
                for (int mt = 0; mt < 4; mt++)
                    LDSM_X4(afr[nxt][mt], aB + c + mt * 2048);
                #pragma unroll
                for (int g = 0; g < 2; g++)
                    LDSM_X4(bfr[nxt][g], bB + c + g * 2048);
            }
            #pragma unroll
            for (int mt = 0; mt < 4; mt++)
                #pragma unroll
                for (int nt = 0; nt < 4; nt++) {
                    int g = nt >> 1, w = nt & 1;
                    mma_16816(acc[mt][nt], afr[cur][mt],
                              bfr[cur][g][w], bfr[cur][g][w + 2]);
                }
        }
    }

    // --- fused epilogue: cos + ArcFace marginal logits, streaming stores ---
    const int mrow  = m0 + warp_m * 64 + (lane >> 2);
    const int ncol0 = n0 + warp_n * 32 + (lane & 3) * 2;
    #pragma unroll
    for (int mt = 0; mt < 4; mt++) {
        const int m1 = mrow + mt * 16;
        const int m2 = m1 + 8;
        const int lab1 = label[m1];
        const int lab2 = label[m2];
        #pragma unroll
        for (int nt = 0; nt < 4; nt++) {
            int n = ncol0 + nt * 8;
            if (!FULL && n >= C_DIM) continue;
            float c0 = acc[mt][nt][0], c1 = acc[mt][nt][1];
            float c2 = acc[mt][nt][2], c3 = acc[mt][nt][3];
            size_t o1 = (size_t)m1 * C_DIM + n;
            size_t o2 = (size_t)m2 * C_DIM + n;
            st_cs_f2(cos_out + o1, c0, c1);
            st_cs_f2(cos_out + o2, c2, c3);
            float g0 = (n     == lab1) ? af_margin(c0) : AF_SCALE * c0;
            float g1 = (n + 1 == lab1) ? af_margin(c1) : AF_SCALE * c1;
            float g2 = (n     == lab2) ? af_margin(c2) : AF_SCALE * c2;
            float g3 = (n + 1 == lab2) ? af_margin(c3) : AF_SCALE * c3;
            st_cs_f2(marg_out + o1, g0, g1);
            st_cs_f2(marg_out + o2, g2, g3);
        }
    }
}

__global__ void __launch_bounds__(THREADS, 2)
arcface_gemm_kernel(const int* __restrict__ label,
                    float* __restrict__ cos_out, float* __restrict__ marg_out) {
    extern __shared__ char dsmem[];
    const uint32_t sbase = (smem_u32(dsmem) + 1023u) & ~1023u;
    const int n0 = blockIdx.x * BN;
    const int m0 = blockIdx.y * BM;
    if (n0 + BN <= C_DIM)
        gemm_tile<true>(label, cos_out, marg_out, sbase, m0, n0);
    else
        gemm_tile<false>(label, cos_out, marg_out, sbase, m0, n0);
}

// ---------------------------------------------------------------------------
// Launch
// ---------------------------------------------------------------------------
extern "C" void kernel_launch(void* const* d_in, const int* in_sizes, int n_in,
                              void* d_out, int out_size) {
    const float* feat  = (const float*)d_in[0];
    const int*   label = (const int*)d_in[1];
    const float* wts   = (const float*)d_in[2];
    float* cos_out  = (float*)d_out;
    float* marg_out = cos_out + (size_t)B_ROWS * C_DIM;

    // 24096 rows, 16 rows per 512-thread block
    norm_rows_kernel<<<(B_ROWS + C_DIM + 15) / 16, 512>>>(feat, wts);

    cudaFuncSetAttribute(arcface_gemm_kernel,
                         cudaFuncAttributeMaxDynamicSharedMemorySize,
                         SMEM_BYTES);

    dim3 grid((C_DIM + BN - 1) / BN, B_ROWS / BM);   // (157, 32)

    // PDL launch: GEMM may start while norm drains; it blocks at
    // griddepcontrol.wait before touching g_f16/g_w16. Falls back to a
    // plain launch if the attribute is rejected (wait is then a no-op).
    cudaLaunchConfig_t cfg = {};
    cfg.gridDim = grid;
    cfg.blockDim = dim3(THREADS, 1, 1);
    cfg.dynamicSmemBytes = SMEM_BYTES;
    cfg.stream = 0;
    cudaLaunchAttribute attr[1];
    attr[0].id = cudaLaunchAttributeProgrammaticStreamSerialization;
    attr[0].val.programmaticStreamSerializationAllowed = 1;
    cfg.attrs = attr;
    cfg.numAttrs = 1;
    cudaError_t err = cudaLaunchKernelEx(&cfg, arcface_gemm_kernel,
                                         label, cos_out, marg_out);
    if (err != cudaSuccess) {
        arcface_gemm_kernel<<<grid, THREADS, SMEM_BYTES>>>(label, cos_out,
                                                           marg_out);
    }
}